// round 13
// baseline (speedup 1.0000x reference)
#include <cuda_runtime.h>
#include <cuda_bf16.h>
#include <math.h>

#define NBINS 128
#define NFREQ 64
#define NKERN 3
#define MLPH  64
#define KPB   20   // keys per block -> grid 410; 3 blocks/SM capacity
#define TPB   256
#define JKEYS 5    // keys per thread

typedef unsigned long long ull;

// Planar coefficient table: g_C[f][coord][bin], coord 0..6 =
//   [A0, A1c, A1s, A2c, A2s, A3c, A3s]
__device__ float4 g_C4[(NFREQ + 1) * 7 * NBINS / 4];

__device__ __forceinline__ void fma2(ull& acc, ull a, ull b) {
    asm("fma.rn.f32x2 %0, %1, %2, %0;" : "+l"(acc) : "l"(a), "l"(b));
}
__device__ __forceinline__ ull dup2(float v) {
    ull r;
    asm("mov.b64 %0, {%1, %1};" : "=l"(r) : "f"(v));
    return r;
}
__device__ __forceinline__ float2 unpack2(ull v) {
    float2 r;
    asm("mov.b64 {%0, %1}, %2;" : "=f"(r.x), "=f"(r.y) : "l"(v));
    return r;
}

// I_k(kappa) via Horner series in h2 = (kappa/2)^2, no divisions.
__global__ void precompute_fourier(const float* __restrict__ mu,
                                   const float* __restrict__ kappa,
                                   const float* __restrict__ weight,
                                   const float* __restrict__ ref_angles) {
    int idx = blockIdx.x * blockDim.x + threadIdx.x;
    if (idx >= NBINS * NFREQ) return;
    int b = idx / NFREQ;
    int f = idx % NFREQ;
    float C[7];
    #pragma unroll
    for (int i = 0; i < 7; i++) C[i] = 0.f;

    #pragma unroll
    for (int m = 0; m < NKERN; m++) {
        int off = (b * NFREQ + f) * NKERN + m;
        float kp = kappa[off];
        float w  = weight[off];
        float me = mu[off] + ref_angles[f];
        float h  = 0.5f * kp;
        float h2 = h * h;
        float ek = __expf(-kp);
        float P0 = fmaf(h2, fmaf(h2, fmaf(h2, fmaf(h2, fmaf(h2, fmaf(h2,
                    1.9290123e-6f, 6.9444444e-5f), 1.7361111e-3f), 2.7777778e-2f),
                    0.25f), 1.0f), 1.0f);
        float P1 = fmaf(h2, fmaf(h2, fmaf(h2, fmaf(h2, fmaf(h2, fmaf(h2,
                    2.7557319e-7f, 1.1574074e-5f), 3.4722222e-4f), 6.9444444e-3f),
                    8.3333333e-2f), 0.5f), 1.0f);
        float P2 = fmaf(h2, fmaf(h2, fmaf(h2, fmaf(h2, fmaf(h2, fmaf(h2,
                    3.4446e-8f, 1.6534392e-6f), 5.7870370e-5f), 1.3888889e-3f),
                    2.0833333e-2f), 1.6666667e-1f), 0.5f);
        float P3 = fmaf(h2, fmaf(h2, fmaf(h2, fmaf(h2, fmaf(h2, fmaf(h2,
                    3.83e-9f, 2.0667e-7f), 8.2671958e-6f), 2.3148148e-4f),
                    4.1666667e-3f), 4.1666667e-2f), 1.6666667e-1f);
        float I0 = P0;
        float I1 = h * P1;
        float I2 = h2 * P2;
        float I3 = h2 * h * P3;

        float cm, sm;
        __sincosf(me, &sm, &cm);
        float wek = w * ek;
        C[0] += wek * I0;
        float g1 = 2.f * wek * I1;
        C[1] += g1 * cm;
        C[2] += g1 * sm;
        float c2 = cm * cm - sm * sm;
        float s2 = 2.f * cm * sm;
        float g2 = 2.f * wek * I2;
        C[3] += g2 * c2;
        C[4] += g2 * s2;
        float c3 = c2 * cm - s2 * sm;
        float s3 = s2 * cm + c2 * sm;
        float g3 = 2.f * wek * I3;
        C[5] += g3 * c3;
        C[6] += g3 * s3;
    }
    float* gC = (float*)g_C4;
    #pragma unroll
    for (int c = 0; c < 7; c++)
        gC[(f * 7 + c) * NBINS + b] = C[c];
}

// dynamic smem (floats):
//   sl[20*128] @ 0  | union { X4[64*20] float4 | w1T[128*66]+h[20*64]+b1w2[128] }
#define OFF_U    (KPB * NBINS)                 // 2560
#define OFF_H    (OFF_U + 128 * 66)            // 11008
#define OFF_B1W2 (OFF_H + KPB * MLPH)          // 12288
#define SMEM_BYTES ((OFF_B1W2 + 2 * MLPH) * 4) // 49664

__global__ __launch_bounds__(TPB, 3)
void key_pruning_main(const float2* __restrict__ K2,
                      const int*    __restrict__ pos,
                      const float*  __restrict__ bias,
                      const float*  __restrict__ W1,      // [64][128]
                      const float*  __restrict__ b1,
                      const float*  __restrict__ W2,
                      const float*  __restrict__ b2,
                      const float*  __restrict__ araw,
                      float*        __restrict__ out,
                      int n) {
    extern __shared__ float sm[];
    float4* X4 = (float4*)(sm + OFF_U);

    const int tid  = threadIdx.x;
    const int warp = tid >> 5;
    const int lane = tid & 31;
    const int key0 = blockIdx.x * KPB;

    // ---- Phase 1: compact features {mag, 2*c1, x, y} ----
    for (int i = tid; i < KPB * NFREQ; i += TPB) {
        int kk = i / NFREQ;
        int f  = i & (NFREQ - 1);
        int key = key0 + kk; if (key >= n) key = n - 1;
        float2 v = K2[key * NFREQ + f];
        float r2 = fmaf(v.x, v.x, v.y * v.y);
        r2 = fmaxf(r2, 1e-30f);
        float rinv = rsqrtf(r2);
        float mag = r2 * rinv;
        float c1x2 = 2.f * v.x * rinv;
        X4[f * KPB + kk] = make_float4(mag, c1x2, v.x, v.y);
    }
    __syncthreads();

    // ---- Phase 2: logits GEMM. warp = 20 keys x 32 bins; f split across warp-halves.
    //      Thread: 5 keys x 4 bins (packed f32x2 bin-pairs). ----
    const int fbase = (warp >= 4) ? 32 : 0;
    const int wb    = (warp & 3) * 32;
    const int kq    = lane >> 3;
    const int b0    = wb + (lane & 7) * 4;   // thread bins b0..b0+3
    const int kbase = kq * JKEYS;

    ull acc[2 * JKEYS];
    #pragma unroll
    for (int i = 0; i < 2 * JKEYS; i++) acc[i] = 0ull;

    const float* gC = (const float*)g_C4;
    const float* Cf = gC + fbase * 7 * NBINS + b0;

    for (int fo = 0; fo < 32; fo++) {
        int f = fbase + fo;
        ulonglong2 Cc[7];
        #pragma unroll
        for (int c = 0; c < 7; c++)
            Cc[c] = *(const ulonglong2*)(Cf + c * NBINS);
        Cf += 7 * NBINS;
        #pragma unroll
        for (int j = 0; j < JKEYS; j++) {
            float4 x = X4[f * KPB + kbase + j];
            float xs0 = x.x;                        // m
            float c1x2 = x.y;                       // 2*cos1
            float xs1 = x.z;                        // m*cos1
            float xs2 = x.w;                        // m*sin1
            float xs3 = fmaf(c1x2, xs1, -xs0);      // m*cos2
            float xs4 = c1x2 * xs2;                 // m*sin2
            float xs5 = fmaf(c1x2, xs3, -xs1);      // m*cos3
            float xs6 = fmaf(c1x2, xs4, -xs2);      // m*sin3
            ull* a = &acc[2 * j];
            { ull d = dup2(xs0); fma2(a[0], d, Cc[0].x); fma2(a[1], d, Cc[0].y); }
            { ull d = dup2(xs1); fma2(a[0], d, Cc[1].x); fma2(a[1], d, Cc[1].y); }
            { ull d = dup2(xs2); fma2(a[0], d, Cc[2].x); fma2(a[1], d, Cc[2].y); }
            { ull d = dup2(xs3); fma2(a[0], d, Cc[3].x); fma2(a[1], d, Cc[3].y); }
            { ull d = dup2(xs4); fma2(a[0], d, Cc[4].x); fma2(a[1], d, Cc[4].y); }
            { ull d = dup2(xs5); fma2(a[0], d, Cc[5].x); fma2(a[1], d, Cc[5].y); }
            { ull d = dup2(xs6); fma2(a[0], d, Cc[6].x); fma2(a[1], d, Cc[6].y); }
        }
    }

    // f-split reduction into sl (low-f warps write with bias; high-f warps add)
    float4 bias4 = *(const float4*)&bias[b0];
    if (warp < 4) {
        #pragma unroll
        for (int j = 0; j < JKEYS; j++) {
            float2 p0 = unpack2(acc[2 * j]);
            float2 p1 = unpack2(acc[2 * j + 1]);
            float4 o = make_float4(p0.x + bias4.x, p0.y + bias4.y,
                                   p1.x + bias4.z, p1.y + bias4.w);
            *(float4*)&sm[(kbase + j) * NBINS + b0] = o;
        }
    }
    __syncthreads();
    if (warp >= 4) {
        #pragma unroll
        for (int j = 0; j < JKEYS; j++) {
            float2 p0 = unpack2(acc[2 * j]);
            float2 p1 = unpack2(acc[2 * j + 1]);
            float4 cur = *(float4*)&sm[(kbase + j) * NBINS + b0];
            cur.x += p0.x; cur.y += p0.y; cur.z += p1.x; cur.w += p1.y;
            *(float4*)&sm[(kbase + j) * NBINS + b0] = cur;
        }
    } else {
        // ---- Phase 3 (overlapped): stage transposed W1 [k][h], stride 66 ----
        for (int i = tid; i < MLPH * NBINS; i += 128) {
            int h = i >> 7;
            int k = i & 127;
            sm[OFF_U + k * 66 + h] = W1[i];
        }
        if (tid < MLPH) {
            sm[OFF_B1W2 + tid]        = b1[tid];
            sm[OFF_B1W2 + MLPH + tid] = W2[tid];
        }
    }
    __syncthreads();

    // ---- Phase 4: MLP layer 1 on all 256 threads: 5 keys x 1 hidden per thread ----
    {
        int hb  = tid & 63;            // hidden unit
        int pkq = tid >> 6;            // key quarter (uniform per warp-half)
        float a[JKEYS];
        #pragma unroll
        for (int j = 0; j < JKEYS; j++) a[j] = 0.f;
        #pragma unroll 4
        for (int k = 0; k < NBINS; k++) {
            float w = sm[OFF_U + k * 66 + hb];
            #pragma unroll
            for (int j = 0; j < JKEYS; j++) {
                float l = sm[(pkq * JKEYS + j) * NBINS + k];
                a[j] = fmaf(l, w, a[j]);
            }
        }
        float bb = sm[OFF_B1W2 + hb];
        float w2 = sm[OFF_B1W2 + MLPH + hb];
        #pragma unroll
        for (int j = 0; j < JKEYS; j++) {
            float h = fmaxf(a[j] + bb, 0.f) * w2;
            sm[OFF_H + (pkq * JKEYS + j) * MLPH + hb] = h;
        }
    }
    __syncthreads();

    // ---- Phase 5: reduce, position weight, sigmoid ----
    if (tid < KPB && (key0 + tid) < n) {
        float s = b2[0];
        const float4* hp = (const float4*)&sm[OFF_H + tid * MLPH];
        float s1 = 0.f, s2 = 0.f, s3 = 0.f;
        #pragma unroll
        for (int j = 0; j < MLPH / 4; j++) {
            float4 v = hp[j];
            s += v.x; s1 += v.y; s2 += v.z; s3 += v.w;
        }
        s = (s + s1) + (s2 + s3);

        int p = pos[key0 + tid];
        float lp = log10f(fmaxf((float)p, 1.0f));
        float a0 = log1pf(expf(araw[0]));
        float a1 = log1pf(expf(araw[1]));
        float a2 = log1pf(expf(araw[2]));
        float w;
        if (lp < 3.f)      w = a0;
        else if (lp < 4.f) w = a0 + (a1 - a0) * (lp - 3.f);
        else if (lp < 5.f) w = a1 + (a2 - a1) * (lp - 4.f);
        else               w = a2;

        float z = s * w;
        out[key0 + tid] = 1.f / (1.f + expf(-z));
    }
}

extern "C" void kernel_launch(void* const* d_in, const int* in_sizes, int n_in,
                              void* d_out, int out_size) {
    const float* K      = (const float*)d_in[0];
    const int*   pos    = (const int*)  d_in[1];
    const float* ra     = (const float*)d_in[2];
    const float* mu     = (const float*)d_in[3];
    const float* kappa  = (const float*)d_in[4];
    const float* weight = (const float*)d_in[5];
    const float* bias   = (const float*)d_in[6];
    const float* W1     = (const float*)d_in[7];
    const float* b1     = (const float*)d_in[8];
    const float* W2     = (const float*)d_in[9];
    const float* b2     = (const float*)d_in[10];
    const float* araw   = (const float*)d_in[11];

    int n = in_sizes[1];   // number of keys

    static int smem_set = 0;
    if (!smem_set) {
        cudaFuncSetAttribute(key_pruning_main,
                             cudaFuncAttributeMaxDynamicSharedMemorySize, SMEM_BYTES);
        smem_set = 1;
    }

    precompute_fourier<<<(NBINS * NFREQ + 127) / 128, 128>>>(mu, kappa, weight, ra);

    int grid = (n + KPB - 1) / KPB;
    key_pruning_main<<<grid, TPB, SMEM_BYTES>>>((const float2*)K, pos, bias, W1, b1, W2, b2, araw,
                                                (float*)d_out, n);
}